// round 2
// baseline (speedup 1.0000x reference)
#include <cuda_runtime.h>

typedef unsigned long long u64;

#define NB 1024
#define SL 512
#define NL 64

__device__ __forceinline__ u64 fma2(u64 a, u64 b, u64 c) {
    u64 d;
    asm("fma.rn.f32x2 %0, %1, %2, %3;" : "=l"(d) : "l"(a), "l"(b), "l"(c));
    return d;
}
__device__ __forceinline__ u64 add2(u64 a, u64 b) {
    u64 d;
    asm("add.rn.f32x2 %0, %1, %2;" : "=l"(d) : "l"(a), "l"(b));
    return d;
}
__device__ __forceinline__ u64 pack2(float lo, float hi) {
    u64 d;
    asm("mov.b64 %0, {%1, %2};" : "=l"(d) : "f"(lo), "f"(hi));
    return d;
}
__device__ __forceinline__ void unpack2(u64 a, float& lo, float& hi) {
    asm("mov.b64 {%0, %1}, %2;" : "=f"(lo), "=f"(hi) : "l"(a));
}

// One WARP = one batch element. Lane j owns labels j and j+32.
//
// Multiplicative recurrence: state q_j with implicit log-scale Z:
//   score_j = ln(q_j) + Z.
// Step:  s_j = sum_i q_i * E_ij   (E = exp(transitions), in registers)
//        q'_j = s_j * exp(em_j - C_t),   Z += C_t
// where C_t = ln(q_0^{t-1}) + em_0^t is a scalar published by lane 0 one step
// in advance (delayed normalizer). No per-step log on the critical path:
// exp(em - C) is issued at the top of the step (hidden under the FMA tree),
// and lane 0's __logf(s_0) runs after its FMUL, off the main chain.
//
// q exchange via 256B smem double buffer, one __syncwarp per step.
__global__ __launch_bounds__(32) void crf_fwd_kernel(
    const float* __restrict__ emissions,
    const int*   __restrict__ mask,
    const float* __restrict__ trans,
    const float* __restrict__ startt,
    const float* __restrict__ endt,
    float* __restrict__ out)
{
    __shared__ __align__(16) u64 qbuf[2][32];
    __shared__ float csm[2];

    const int lane = threadIdx.x;
    const int b    = blockIdx.x;
    const size_t ebase = (size_t)b * SL * NL;
    const int ca = lane;          // first column owned by this lane
    const int cb = lane + 32;     // second column

    // E columns for ca and cb, pairs packed over rows (i, i+32) to match the
    // q smem layout: qbuf[m] = (q_m, q_{m+32}).
    u64 Ea[32], Eb[32];
#pragma unroll
    for (int m = 0; m < 32; m++) {
        Ea[m] = pack2(__expf(trans[m * NL + ca]), __expf(trans[(m + 32) * NL + ca]));
        Eb[m] = pack2(__expf(trans[m * NL + cb]), __expf(trans[(m + 32) * NL + cb]));
    }
    const float fend_a = __expf(endt[ca]);
    const float fend_b = __expf(endt[cb]);

    // t = 0: score = start + em0; normalize by lane 0's score of label 0.
    float sc_a = startt[ca] + emissions[ebase + ca];
    float sc_b = startt[cb] + emissions[ebase + cb];
    const float z0 = __shfl_sync(0xffffffffu, sc_a, 0);
    float qa = __expf(sc_a - z0);
    float qb = __expf(sc_b - z0);
    float Z = z0;
    float d = 0.0f;                       // ln q_0 (exactly 0 at t=0)

    // prefetch t = 1
    float ea_n = emissions[ebase + NL + ca];
    float eb_n = emissions[ebase + NL + cb];
    int   mk_n = mask[b * SL + 1];

    qbuf[0][lane] = pack2(qa, qb);
    if (lane == 0) csm[0] = d + ea_n;     // C_1 = ln q_0^0 + em_0^1

#pragma unroll 2
    for (int t = 1; t < SL; t++) {
        __syncwarp();
        const int pb  = (t - 1) & 1;
        const int cbf = t & 1;
        const float C    = csm[pb];
        const float em_a = ea_n;
        const float em_b = eb_n;
        const int   mk   = mk_n;

        // prefetch t+1 (clamped; last-iter values unused)
        int tn = t + 1; if (tn >= SL) tn = SL - 1;
        ea_n = emissions[ebase + (size_t)tn * NL + ca];
        eb_n = emissions[ebase + (size_t)tn * NL + cb];
        mk_n = mask[b * SL + tn];

        // exps issued early — hidden under the FMA tree
        const float cfa = __expf(em_a - C);
        const float cfb = __expf(em_b - C);

        // s_j = sum_i q_i * E_ij, packed f32x2, 4 accumulators per column
        const ulonglong2* qp = (const ulonglong2*)qbuf[pb];
        u64 a0 = 0, a1 = 0, a2 = 0, a3 = 0;
        u64 b0 = 0, b1 = 0, b2 = 0, b3 = 0;
#pragma unroll
        for (int k = 0; k < 8; k++) {
            ulonglong2 v0 = qp[2 * k];
            ulonglong2 v1 = qp[2 * k + 1];
            a0 = fma2(v0.x, Ea[4 * k + 0], a0);  b0 = fma2(v0.x, Eb[4 * k + 0], b0);
            a1 = fma2(v0.y, Ea[4 * k + 1], a1);  b1 = fma2(v0.y, Eb[4 * k + 1], b1);
            a2 = fma2(v1.x, Ea[4 * k + 2], a2);  b2 = fma2(v1.x, Eb[4 * k + 2], b2);
            a3 = fma2(v1.y, Ea[4 * k + 3], a3);  b3 = fma2(v1.y, Eb[4 * k + 3], b3);
        }
        float xa, ya, xb, yb;
        unpack2(add2(add2(a0, a1), add2(a2, a3)), xa, ya);
        unpack2(add2(add2(b0, b1), add2(b2, b3)), xb, yb);
        const float s_a = xa + ya;
        const float s_b = xb + yb;

        if (mk) {
            qa = s_a * cfa;
            qb = s_b * cfb;
            Z += C;
        }
        if (lane == 0) {
            if (mk) d = __logf(s_a) + (em_a - C);   // ln q_0^t
            csm[cbf] = d + ea_n;                    // C_{t+1} = ln q_0^t + em_0^{t+1}
        }
        qbuf[cbf][lane] = pack2(qa, qb);
    }

    // out[b] = Z + ln( sum_j q_j * exp(end_j) )
    float v = qa * fend_a + qb * fend_b;
#pragma unroll
    for (int o = 16; o; o >>= 1) v += __shfl_xor_sync(0xffffffffu, v, o);
    if (lane == 0) out[b] = Z + __logf(v);
}

extern "C" void kernel_launch(void* const* d_in, const int* in_sizes, int n_in,
                              void* d_out, int out_size) {
    const float* emissions = (const float*)d_in[0];
    const int*   msk       = (const int*)d_in[1];
    const float* trans     = (const float*)d_in[2];
    const float* startt    = (const float*)d_in[3];
    const float* endt      = (const float*)d_in[4];
    crf_fwd_kernel<<<NB, 32>>>(emissions, msk, trans, startt, endt, (float*)d_out);
}

// round 3
// speedup vs baseline: 1.1159x; 1.1159x over previous
#include <cuda_runtime.h>

typedef unsigned long long u64;

#define NB 1024
#define SL 512
#define NL 64

__device__ __forceinline__ u64 fma2(u64 a, u64 b, u64 c) {
    u64 d;
    asm("fma.rn.f32x2 %0, %1, %2, %3;" : "=l"(d) : "l"(a), "l"(b), "l"(c));
    return d;
}
__device__ __forceinline__ u64 add2(u64 a, u64 b) {
    u64 d;
    asm("add.rn.f32x2 %0, %1, %2;" : "=l"(d) : "l"(a), "l"(b));
    return d;
}
__device__ __forceinline__ u64 pack2(float lo, float hi) {
    u64 d;
    asm("mov.b64 %0, {%1, %2};" : "=l"(d) : "f"(lo), "f"(hi));
    return d;
}
__device__ __forceinline__ void unpack2(u64 a, float& lo, float& hi) {
    asm("mov.b64 {%0, %1}, %2;" : "=f"(lo), "=f"(hi) : "l"(a));
}

// One 64-thread block = one batch element.
// Split over i (rows): warp w owns rows [32w, 32w+32). Lane l computes
// PARTIAL sums for the adjacent column pair (2l, 2l+1) over its 32 rows:
// 8 LDS.128 (broadcast) + 32 fma2, chain depth 4.
// Partials exchanged via smem; thread t then owns column t for the epilogue.
//
// Multiplicative recurrence (no log on critical path):
//   s_j = sum_i q_i E_ij ;  q'_j = s_j * exp(em_j - C_t) ;  Z += C_t
// with delayed scalar normalizer C_t = ln q_0^{t-1} + em_0^t maintained by
// thread 0 (its __logf runs off the main chain). Mask=0 keeps q and Z.
__global__ __launch_bounds__(64) void crf_fwd_kernel(
    const float* __restrict__ emissions,
    const int*   __restrict__ mask,
    const float* __restrict__ trans,
    const float* __restrict__ startt,
    const float* __restrict__ endt,
    float* __restrict__ out)
{
    __shared__ __align__(16) float qbuf[2][NL];
    __shared__ __align__(8)  float part[2][NL];
    __shared__ float csm[2];
    __shared__ float red[2];

    const int tid = threadIdx.x;
    const int w   = tid >> 5;
    const int l   = tid & 31;
    const int b   = blockIdx.x;
    const size_t ebase = (size_t)b * SL * NL;

    const int pca = 2 * l;        // partial columns computed by this thread
    const int pcb = 2 * l + 1;
    const int oc  = tid;          // owned column for the epilogue

    // E for rows 32w + [0,32), cols pca/pcb, packed over adjacent row pairs
    // to match q's natural-order smem layout.
    u64 Ea[16], Eb[16];
#pragma unroll
    for (int m = 0; m < 16; m++) {
        const int r = 32 * w + 2 * m;
        Ea[m] = pack2(__expf(trans[r * NL + pca]), __expf(trans[(r + 1) * NL + pca]));
        Eb[m] = pack2(__expf(trans[r * NL + pcb]), __expf(trans[(r + 1) * NL + pcb]));
    }
    const float fend = __expf(endt[oc]);

    // t = 0
    float sc = startt[oc] + emissions[ebase + oc];
    if (tid == 0) red[0] = sc;            // broadcast normalizer z0
    __syncthreads();
    const float z0 = red[0];
    float q = __expf(sc - z0);            // this thread's column state
    float Z = z0;
    float d = 0.0f;                       // ln q_0 (thread 0 only meaningful)
    qbuf[0][oc] = q;

    // prefetch t = 1
    float em_n = emissions[ebase + NL + oc];
    int   mk_n = mask[b * SL + 1];
    if (tid == 0) csm[0] = d + em_n;      // C_1 = ln q_0^0 + em_0^1

#pragma unroll 2
    for (int t = 1; t < SL; t++) {
        __syncthreads();                  // publishes qbuf[pb], csm[pb]
        const int pb  = (t - 1) & 1;
        const int cbf = t & 1;
        const float C  = csm[pb];
        const float em = em_n;
        const int   mk = mk_n;

        int tn = t + 1; if (tn >= SL) tn = SL - 1;
        em_n = emissions[ebase + (size_t)tn * NL + oc];
        mk_n = mask[b * SL + tn];

        // issued early, hidden under the FMA tree
        const float cf = __expf(em - C);

        // partial matvec over this warp's 32 rows
        const ulonglong2* qp = (const ulonglong2*)(qbuf[pb] + 32 * w);
        u64 a0 = 0, a1 = 0, a2 = 0, a3 = 0;
        u64 c0 = 0, c1 = 0, c2 = 0, c3 = 0;
#pragma unroll
        for (int k = 0; k < 4; k++) {
            ulonglong2 v0 = qp[2 * k];
            ulonglong2 v1 = qp[2 * k + 1];
            a0 = fma2(v0.x, Ea[4 * k + 0], a0);  c0 = fma2(v0.x, Eb[4 * k + 0], c0);
            a1 = fma2(v0.y, Ea[4 * k + 1], a1);  c1 = fma2(v0.y, Eb[4 * k + 1], c1);
            a2 = fma2(v1.x, Ea[4 * k + 2], a2);  c2 = fma2(v1.x, Eb[4 * k + 2], c2);
            a3 = fma2(v1.y, Ea[4 * k + 3], a3);  c3 = fma2(v1.y, Eb[4 * k + 3], c3);
        }
        float xa, ya, xb, yb;
        unpack2(add2(add2(a0, a1), add2(a2, a3)), xa, ya);
        unpack2(add2(add2(c0, c1), add2(c2, c3)), xb, yb);

        // publish partials for cols (2l, 2l+1): adjacent -> one STS.64
        *(float2*)&part[w][pca] = make_float2(xa + ya, xb + yb);
        __syncthreads();

        // epilogue on owned column
        const float s = part[0][oc] + part[1][oc];
        if (mk) { q = s * cf; Z += C; }
        if (tid == 0) {
            if (mk) d = __logf(s) + (em - C);   // ln q_0^t, off critical path
            csm[cbf] = d + em_n;                // C_{t+1}
        }
        qbuf[cbf][oc] = q;
    }

    // out[b] = Z + ln( sum_j q_j * exp(end_j) )
    float v = q * fend;
#pragma unroll
    for (int o = 16; o; o >>= 1) v += __shfl_xor_sync(0xffffffffu, v, o);
    if (l == 0) red[w] = v;
    __syncthreads();
    if (tid == 0) out[b] = Z + __logf(red[0] + red[1]);
}

extern "C" void kernel_launch(void* const* d_in, const int* in_sizes, int n_in,
                              void* d_out, int out_size) {
    const float* emissions = (const float*)d_in[0];
    const int*   msk       = (const int*)d_in[1];
    const float* trans     = (const float*)d_in[2];
    const float* startt    = (const float*)d_in[3];
    const float* endt      = (const float*)d_in[4];
    crf_fwd_kernel<<<NB, 64>>>(emissions, msk, trans, startt, endt, (float*)d_out);
}